// round 16
// baseline (speedup 1.0000x reference)
#include <cuda_runtime.h>
#include <cuda_fp16.h>
#include <math.h>

#define NN 50000
#define EE 800000
#define HH 64
#define TSCALE 0.015625f   // 2^-6 global scale on (eq, ev); cancels in softmax ratio

#define SCAN_CHUNK 1024
#define SCAN_NB ((NN + SCAN_CHUNK - 1) / SCAN_CHUNK)   // 49

typedef unsigned short u16;
typedef unsigned long long ull;

// ---- scratch (device globals) ----
__device__ uint2  g_T1[NN * 32];   // conv1 per node/lane: (half2 eq*S, half2 ev*S)
__device__ uint2  g_T2[NN * 32];   // conv2 table
__device__ int    g_deg[NN];       // zero at start of every launch (self-cleaned)
__device__ int    g_rowptr[NN + 1];
__device__ u16    g_rank[EE];      // vectorized ushort4 access only
__device__ int    g_ssrc[EE];      // int: scattered stores must be full-word
__device__ int    g_bsum[SCAN_NB];
__device__ int    g_boff[SCAN_NB];
__device__ int    g_ctr;           // last-block counter (self-resetting)
__device__ int    g_ctr2;          // reset counter (self-resetting)
__device__ volatile int g_flag;    // scan barrier flag (self-resetting)

// ---- packed f32x2 helpers ----
__device__ __forceinline__ ull PK(float x, float y) {
    float2 f = make_float2(x, y);
    return *(ull*)&f;
}
__device__ __forceinline__ ull ADD2(ull a, ull b) {
    ull r; asm("add.rn.f32x2 %0, %1, %2;" : "=l"(r) : "l"(a), "l"(b)); return r;
}
__device__ __forceinline__ ull FMA2(ull a, ull b, ull c) {
    ull r; asm("fma.rn.f32x2 %0, %1, %2, %3;" : "=l"(r) : "l"(a), "l"(b), "l"(c)); return r;
}

// ---------------- CSR build (R13-proven plain launches) ----------------
__global__ void k_hist(const int4* __restrict__ dst4) {
    int i = blockIdx.x * blockDim.x + threadIdx.x;
    if (i < EE / 8) {
        int4 da = dst4[2 * i];
        int4 db = dst4[2 * i + 1];
        u16 a0 = (u16)atomicAdd(&g_deg[da.x], 1);
        u16 a1 = (u16)atomicAdd(&g_deg[da.y], 1);
        u16 a2 = (u16)atomicAdd(&g_deg[da.z], 1);
        u16 a3 = (u16)atomicAdd(&g_deg[da.w], 1);
        u16 b0 = (u16)atomicAdd(&g_deg[db.x], 1);
        u16 b1 = (u16)atomicAdd(&g_deg[db.y], 1);
        u16 b2 = (u16)atomicAdd(&g_deg[db.z], 1);
        u16 b3 = (u16)atomicAdd(&g_deg[db.w], 1);
        *(ushort4*)&g_rank[i * 8]     = make_ushort4(a0, a1, a2, a3);
        *(ushort4*)&g_rank[i * 8 + 4] = make_ushort4(b0, b1, b2, b3);
    }
}

__global__ void k_scanBC() {
    int t = threadIdx.x, b = blockIdx.x;
    int gbase = b * SCAN_CHUNK + t * 4;
    int4 v = make_int4(0, 0, 0, 0);
    if (gbase < NN) {
        v = *(const int4*)&g_deg[gbase];
        *(int4*)&g_deg[gbase] = make_int4(0, 0, 0, 0);   // self-clean
    }
    int tsum = v.x + v.y + v.z + v.w;
    int lane = t & 31, wid = t >> 5;
    int inc = tsum;
#pragma unroll
    for (int d = 1; d < 32; d <<= 1) {
        int a = __shfl_up_sync(0xffffffffu, inc, d);
        if (lane >= d) inc += a;
    }
    __shared__ int swp[8], soff[8], sTot, isLast;
    if (lane == 31) swp[wid] = inc;
    __syncthreads();
    if (t < 8) {
        int vb = swp[t];
        int ib = vb;
#pragma unroll
        for (int d = 1; d < 8; d <<= 1) {
            int a = __shfl_up_sync(0xffu, ib, d);
            if (t >= d) ib += a;
        }
        soff[t] = ib - vb;
        if (t == 7) sTot = ib;
    }
    __syncthreads();

    if (t == 0) {
        g_bsum[b] = sTot;
        __threadfence();
        int done = atomicAdd(&g_ctr, 1);
        isLast = (done == SCAN_NB - 1);
        if (isLast) g_ctr = 0;
    }
    __syncthreads();

    if (isLast) {
        if (t < 32) {
            __threadfence();
            int v0 = (t < SCAN_NB) ? g_bsum[t] : 0;
            int v1 = (t + 32 < SCAN_NB) ? g_bsum[t + 32] : 0;
            int i0 = v0, i1 = v1;
#pragma unroll
            for (int d = 1; d < 32; d <<= 1) {
                int a = __shfl_up_sync(0xffffffffu, i0, d);
                int b2 = __shfl_up_sync(0xffffffffu, i1, d);
                if (t >= d) { i0 += a; i1 += b2; }
            }
            int tot0 = __shfl_sync(0xffffffffu, i0, 31);
            if (t < SCAN_NB) g_boff[t] = i0 - v0;
            if (t + 32 < SCAN_NB) g_boff[t + 32] = tot0 + i1 - v1;
            if (t == 0) {
                g_rowptr[NN] = EE;
                __threadfence();
                g_flag = 1;
            }
        }
    } else {
        if (t == 0) { while (g_flag == 0) { } }
    }
    __syncthreads();

    if (gbase < NN) {
        int base = g_boff[b] + soff[wid] + inc - tsum;
        int4 r;
        r.x = base;
        r.y = base + v.x;
        r.z = r.y + v.y;
        r.w = r.z + v.z;
        *(int4*)&g_rowptr[gbase] = r;
    }
    __syncthreads();
    if (t == 0) {
        int d2 = atomicAdd(&g_ctr2, 1);
        if (d2 == SCAN_NB - 1) { g_ctr2 = 0; g_flag = 0; }
    }
}

// 8 edges per thread. PDL primary for conv1_proj2.
__global__ void k_scatter(const int4* __restrict__ src4, const int4* __restrict__ dst4) {
#if __CUDA_ARCH__ >= 900
    cudaTriggerProgrammaticLaunchCompletion();
#endif
    int i = blockIdx.x * blockDim.x + threadIdx.x;
    if (i < EE / 8) {
        int4 sa = *(const int4*)&src4[2 * i];
        int4 sb = *(const int4*)&src4[2 * i + 1];
        int4 da = *(const int4*)&dst4[2 * i];
        int4 db = *(const int4*)&dst4[2 * i + 1];
        ushort4 ra = *(const ushort4*)&g_rank[i * 8];
        ushort4 rb = *(const ushort4*)&g_rank[i * 8 + 4];
        int pa0 = __ldg(&g_rowptr[da.x]) + ra.x;
        int pa1 = __ldg(&g_rowptr[da.y]) + ra.y;
        int pa2 = __ldg(&g_rowptr[da.z]) + ra.z;
        int pa3 = __ldg(&g_rowptr[da.w]) + ra.w;
        int pb0 = __ldg(&g_rowptr[db.x]) + rb.x;
        int pb1 = __ldg(&g_rowptr[db.y]) + rb.y;
        int pb2 = __ldg(&g_rowptr[db.z]) + rb.z;
        int pb3 = __ldg(&g_rowptr[db.w]) + rb.w;
        g_ssrc[pa0] = sa.x; g_ssrc[pa1] = sa.y;
        g_ssrc[pa2] = sa.z; g_ssrc[pa3] = sa.w;
        g_ssrc[pb0] = sb.x; g_ssrc[pb1] = sb.y;
        g_ssrc[pb2] = sb.z; g_ssrc[pb3] = sb.w;
    }
}

// ---------------- fp16 table store ----------------
__device__ __forceinline__ void store_T(uint2* __restrict__ T, int node, int lane,
                                        float eq0, float eq1, float ev0, float ev1) {
    uint2 u;
    half2 heq = __floats2half2_rn(eq0 * TSCALE, eq1 * TSCALE);
    half2 hev = __floats2half2_rn(ev0 * TSCALE, ev1 * TSCALE);
    *(half2*)&u.x = heq;
    *(half2*)&u.y = hev;
    T[node * 32 + lane] = u;
}

// ---------------- conv1 projections (in=3) ----------------
__global__ void k_proj3(const float* __restrict__ x, const float* __restrict__ pos,
                        const float* __restrict__ Wsrc, const float* __restrict__ Wval,
                        const float* __restrict__ Wpos) {
    int lane = threadIdx.x & 31;
    int wid = threadIdx.x >> 5;
    int base = (blockIdx.x * 8 + wid) * 4;
    int c = 2 * lane;

    float2 ws0 = *(const float2*)&Wsrc[0 * HH + c];
    float2 ws1 = *(const float2*)&Wsrc[1 * HH + c];
    float2 ws2 = *(const float2*)&Wsrc[2 * HH + c];
    float2 wv0 = *(const float2*)&Wval[0 * HH + c];
    float2 wv1 = *(const float2*)&Wval[1 * HH + c];
    float2 wv2 = *(const float2*)&Wval[2 * HH + c];
    float2 wp0 = *(const float2*)&Wpos[0 * HH + c];
    float2 wp1 = *(const float2*)&Wpos[1 * HH + c];
    float2 wp2 = *(const float2*)&Wpos[2 * HH + c];

#pragma unroll
    for (int j = 0; j < 4; j++) {
        int node = base + j;
        if (node >= NN) break;
        float x0 = __ldg(&x[node * 3 + 0]);
        float x1 = __ldg(&x[node * 3 + 1]);
        float x2 = __ldg(&x[node * 3 + 2]);
        float p0 = __ldg(&pos[node * 3 + 0]);
        float p1 = __ldg(&pos[node * 3 + 1]);
        float p2 = __ldg(&pos[node * 3 + 2]);

        float qx = x0 * ws0.x + x1 * ws1.x + x2 * ws2.x;
        float qy = x0 * ws0.y + x1 * ws1.y + x2 * ws2.y;
        float vx = x0 * wv0.x + x1 * wv1.x + x2 * wv2.x;
        float vy = x0 * wv0.y + x1 * wv1.y + x2 * wv2.y;
        float ppx = p0 * wp0.x + p1 * wp1.x + p2 * wp2.x;
        float ppy = p0 * wp0.y + p1 * wp1.y + p2 * wp2.y;

        float eq0 = __expf(-(qx + ppx));
        float eq1 = __expf(-(qy + ppy));
        store_T(g_T1, node, lane, eq0, eq1, eq0 * (vx - ppx), eq1 * (vy - ppy));
    }
}

// ---------------- edge core (R8-proven; dc passed in) ----------------
__device__ __forceinline__ void acc1(const uint2* __restrict__ Tl, int sn, ull& s, ull& a) {
    uint2 t = __ldg(&Tl[sn * 32]);
    float2 eq = __half22float2(*(const half2*)&t.x);
    float2 ev = __half22float2(*(const half2*)&t.y);
    s = ADD2(s, PK(eq.x, eq.y));
    a = ADD2(a, PK(ev.x, ev.y));
}

__device__ __forceinline__ float2 edge_node(const uint2* __restrict__ T,
                                            int w, int lane, float2 dc) {
    int beg = __ldg(&g_rowptr[w]), end = __ldg(&g_rowptr[w + 1]);
    const uint2* Tl = &T[lane];
    ull s0 = 0ull, a0 = 0ull, s1 = 0ull, a1 = 0ull;

    for (int base = beg; base < end; base += 32) {
        int rem = end - base;
        int n = rem < 32 ? rem : 32;
        int idx = __ldg(&g_ssrc[base + (lane < n ? lane : 0)]);
        int j = 0;
        for (; j + 4 <= n; j += 4) {
            int sn0 = __shfl_sync(0xffffffffu, idx, j + 0);
            int sn1 = __shfl_sync(0xffffffffu, idx, j + 1);
            int sn2 = __shfl_sync(0xffffffffu, idx, j + 2);
            int sn3 = __shfl_sync(0xffffffffu, idx, j + 3);
            acc1(Tl, sn0, s0, a0);
            acc1(Tl, sn1, s1, a1);
            acc1(Tl, sn2, s0, a0);
            acc1(Tl, sn3, s1, a1);
        }
        for (; j < n; j++) {
            int sn = __shfl_sync(0xffffffffu, idx, j);
            acc1(Tl, sn, s0, a0);
        }
    }
    ull s = ADD2(s0, s1), a = ADD2(a0, a1);

    float2 r;
    if (end > beg) {
        float2 sf = *(float2*)&s;
        float2 af = *(float2*)&a;
        r.x = fmaxf(__fdividef(af.x, sf.x + 1e-12f) + dc.x, 0.f);
        r.y = fmaxf(__fdividef(af.y, sf.y + 1e-12f) + dc.y, 0.f);
    } else {
        r = make_float2(0.f, 0.f);
    }
    return r;
}

// ---- conv1 edge pass + conv2 projections, block-phase fused ----
// Phase 1: WORK-STOLEN gathers (smem counter) -> shx. Phase 2: static matvec.
__global__ __launch_bounds__(512)
void k_conv1_proj2(const float* __restrict__ pos,
                   const float* __restrict__ W1pos, const float* __restrict__ b1pos,
                   const float* __restrict__ Wsrc, const float* __restrict__ Wval,
                   const float* __restrict__ Wpos) {
    __shared__ float shx[64][HH];      // 16 KB
    __shared__ ull sWs[HH * 32];       // 16 KB
    __shared__ ull sWv[HH * 32];       // 16 KB
    __shared__ int sCtr;
    int tid = threadIdx.x;
    int lane = tid & 31, wid = tid >> 5;
    int nodeBase = blockIdx.x * 64;
    int c = 2 * lane;

#if __CUDA_ARCH__ >= 900
    cudaTriggerProgrammaticLaunchCompletion();
#endif

    // staging: inputs only — safe before grid-dep sync
    const ull* Ws8 = (const ull*)Wsrc;
    const ull* Wv8 = (const ull*)Wval;
    for (int i = tid; i < HH * 32; i += 512) {
        sWs[i] = Ws8[i];
        sWv[i] = Wv8[i];
    }
    if (tid == 0) sCtr = 0;

    float2 u0 = *(const float2*)&W1pos[0 * HH + c];
    float2 u1 = *(const float2*)&W1pos[1 * HH + c];
    float2 u2 = *(const float2*)&W1pos[2 * HH + c];
    float2 b1 = *(const float2*)&b1pos[c];
    float2 wp0 = *(const float2*)&Wpos[0 * HH + c];
    float2 wp1 = *(const float2*)&Wpos[1 * HH + c];
    float2 wp2 = *(const float2*)&Wpos[2 * HH + c];

#if __CUDA_ARCH__ >= 900
    cudaGridDependencySynchronize();   // scatter (and all prior) complete
#endif
    __syncthreads();                   // sCtr init visible

    // ---- phase 1: work-stolen gathers ----
    for (;;) {
        int j;
        if (lane == 0) j = atomicAdd(&sCtr, 1);
        j = __shfl_sync(0xffffffffu, j, 0);
        if (j >= 64) break;
        int node = nodeBase + j;
        float2 hv = make_float2(0.f, 0.f);
        if (node < NN) {
            float p0 = __ldg(&pos[node * 3 + 0]);
            float p1 = __ldg(&pos[node * 3 + 1]);
            float p2 = __ldg(&pos[node * 3 + 2]);
            float2 dc = make_float2(p0 * u0.x + p1 * u1.x + p2 * u2.x + b1.x,
                                    p0 * u0.y + p1 * u1.y + p2 * u2.y + b1.y);
            hv = edge_node(g_T1, node, lane, dc);
        }
        *(float2*)&shx[j][2 * lane] = hv;
    }
    __syncthreads();

    // ---- phase 2: conv2 projections, static warp -> 4 rows ----
    int n0 = wid * 4;
    ull aS[4], aV[4];
#pragma unroll
    for (int j = 0; j < 4; j++) { aS[j] = 0ull; aV[j] = 0ull; }

#pragma unroll 8
    for (int k = 0; k < HH; k++) {
        ull ws = sWs[k * 32 + lane];
        ull wv = sWv[k * 32 + lane];
#pragma unroll
        for (int j = 0; j < 4; j++) {
            float xk = shx[n0 + j][k];
            ull xp = PK(xk, xk);
            aS[j] = FMA2(xp, ws, aS[j]);
            aV[j] = FMA2(xp, wv, aV[j]);
        }
    }

#pragma unroll
    for (int j = 0; j < 4; j++) {
        int node = nodeBase + n0 + j;
        if (node >= NN) break;
        float p0 = __ldg(&pos[node * 3 + 0]);
        float p1 = __ldg(&pos[node * 3 + 1]);
        float p2 = __ldg(&pos[node * 3 + 2]);
        float ppx = p0 * wp0.x + p1 * wp1.x + p2 * wp2.x;
        float ppy = p0 * wp0.y + p1 * wp1.y + p2 * wp2.y;
        float2 s = *(float2*)&aS[j];
        float2 v = *(float2*)&aV[j];
        float eq0 = __expf(-(s.x + ppx));
        float eq1 = __expf(-(s.y + ppy));
        store_T(g_T2, node, lane, eq0, eq1, eq0 * (v.x - ppx), eq1 * (v.y - ppy));
    }
}

// conv2 edge pass + MLP head: 64 nodes/block, work-stolen phase 1,
// smem-broadcast matvec phase 2 (no shuffles).
__global__ __launch_bounds__(512)
void k_edge_head(const float* __restrict__ pos,
                 const float* __restrict__ W2pos, const float* __restrict__ b2pos,
                 const float* __restrict__ Wfc1, const float* __restrict__ bfc1,
                 const float* __restrict__ Wfc2, const float* __restrict__ bfc2,
                 float* __restrict__ out) {
    __shared__ float shx[64][HH];    // 16 KB: gathered h
    __shared__ float2 sW[32 * 32];   // 8 KB
    __shared__ float sb1[32], sW2[32];
    __shared__ int sCtr;
    int tid = threadIdx.x;
    int lane = tid & 31, wid = tid >> 5;
    int nodeBase = blockIdx.x * 64;
    int c = 2 * lane;

    // staging: inputs only — safe before grid-dep sync
    for (int i = tid; i < 1024; i += 512) {
        int q = i >> 5, cc = i & 31;
        sW[i] = make_float2(Wfc1[(2 * q) * 32 + cc], Wfc1[(2 * q + 1) * 32 + cc]);
    }
    if (tid < 32) { sb1[tid] = bfc1[tid]; sW2[tid] = Wfc2[tid]; }
    if (tid == 0) sCtr = 0;

    float2 u0 = *(const float2*)&W2pos[0 * HH + c];
    float2 u1 = *(const float2*)&W2pos[1 * HH + c];
    float2 u2 = *(const float2*)&W2pos[2 * HH + c];
    float2 b2p = *(const float2*)&b2pos[c];
    float b2 = bfc2[0];

#if __CUDA_ARCH__ >= 900
    cudaGridDependencySynchronize();   // conv1_proj2 complete
#endif
    __syncthreads();

    // ---- phase 1: work-stolen gathers ----
    for (;;) {
        int j;
        if (lane == 0) j = atomicAdd(&sCtr, 1);
        j = __shfl_sync(0xffffffffu, j, 0);
        if (j >= 64) break;
        int node = nodeBase + j;
        float2 hv = make_float2(0.f, 0.f);
        if (node < NN) {
            float p0 = __ldg(&pos[node * 3 + 0]);
            float p1 = __ldg(&pos[node * 3 + 1]);
            float p2 = __ldg(&pos[node * 3 + 2]);
            float2 dc = make_float2(p0 * u0.x + p1 * u1.x + p2 * u2.x + b2p.x,
                                    p0 * u0.y + p1 * u1.y + p2 * u2.y + b2p.y);
            hv = edge_node(g_T2, node, lane, dc);
        }
        *(float2*)&shx[j][2 * lane] = hv;
    }
    __syncthreads();

    // ---- phase 2: MLP head, static warp -> 4 rows, smem-broadcast h ----
    int n0 = wid * 4;
#pragma unroll
    for (int j = 0; j < 4; j++) {
        int w = nodeBase + n0 + j;
        if (w >= NN) break;
        const float* hr = shx[n0 + j];
        float acc = sb1[lane];
#pragma unroll
        for (int q = 0; q < 32; q++) {
            float2 wv = sW[q * 32 + lane];
            acc = fmaf(hr[2 * q], wv.x, fmaf(hr[2 * q + 1], wv.y, acc));
        }
        acc = fmaxf(acc, 0.f);
        float y = acc * sW2[lane];
#pragma unroll
        for (int off = 16; off; off >>= 1) y += __shfl_xor_sync(0xffffffffu, y, off);
        if (lane == 0) out[w] = y + b2;
    }
}

extern "C" void kernel_launch(void* const* d_in, const int* in_sizes, int n_in,
                              void* d_out, int out_size) {
    const float* x    = (const float*)d_in[0];
    const float* pos  = (const float*)d_in[1];
    const int*   ei   = (const int*)d_in[2];
    const float* W1s  = (const float*)d_in[4];
    const float* W1v  = (const float*)d_in[6];
    const float* W1p  = (const float*)d_in[7];
    const float* b1p  = (const float*)d_in[8];
    const float* W2s  = (const float*)d_in[9];
    const float* W2v  = (const float*)d_in[11];
    const float* W2p  = (const float*)d_in[12];
    const float* b2p  = (const float*)d_in[13];
    const float* Wf1  = (const float*)d_in[14];
    const float* bf1  = (const float*)d_in[15];
    const float* Wf2  = (const float*)d_in[16];
    const float* bf2  = (const float*)d_in[17];
    float* out = (float*)d_out;

    const int4* src4 = (const int4*)ei;
    const int4* dst4 = (const int4*)(ei + EE);

    int vec8Grid = (EE / 8 + 255) / 256;   // 391

    cudaStream_t s2;
    cudaStreamCreate(&s2);
    cudaEvent_t evF, evP;
    cudaEventCreateWithFlags(&evF, cudaEventDisableTiming);
    cudaEventCreateWithFlags(&evP, cudaEventDisableTiming);

    // fork: proj3 on side stream
    cudaEventRecord(evF, 0);
    cudaStreamWaitEvent(s2, evF, 0);
    k_proj3<<<(NN + 31) / 32, 256, 0, s2>>>(x, pos, W1s, W1v, W1p);
    cudaEventRecord(evP, s2);

    // CSR chain on main stream (plain launches — R13-proven)
    k_hist<<<vec8Grid, 256>>>(dst4);
    k_scanBC<<<SCAN_NB, 256>>>();
    cudaStreamWaitEvent(0, evP, 0);
    k_scatter<<<vec8Grid, 256>>>(src4, dst4);

    // PDL launches for the two big edge kernels (R13-proven win)
    cudaLaunchAttribute attrs[1];
    attrs[0].id = cudaLaunchAttributeProgrammaticStreamSerialization;
    attrs[0].val.programmaticStreamSerializationAllowed = 1;

    {
        cudaLaunchConfig_t cfg = {};
        cfg.gridDim = dim3((NN + 63) / 64);
        cfg.blockDim = dim3(512);
        cfg.stream = 0;
        cfg.attrs = attrs;
        cfg.numAttrs = 1;
        cudaLaunchKernelEx(&cfg, k_conv1_proj2, pos, W1p, b1p, W2s, W2v, W2p);
    }
    {
        cudaLaunchConfig_t cfg = {};
        cfg.gridDim = dim3((NN + 63) / 64);
        cfg.blockDim = dim3(512);
        cfg.stream = 0;
        cfg.attrs = attrs;
        cfg.numAttrs = 1;
        cudaLaunchKernelEx(&cfg, k_edge_head, pos, W2p, b2p, Wf1, bf1, Wf2, bf2, out);
    }
}

// round 17
// speedup vs baseline: 1.3614x; 1.3614x over previous
#include <cuda_runtime.h>
#include <cuda_fp16.h>
#include <math.h>

#define NN 50000
#define EE 800000
#define HH 64
#define TSCALE 0.015625f   // 2^-6 global scale on (eq, ev); cancels in softmax ratio

#define SCAN_CHUNK 1024
#define SCAN_NB ((NN + SCAN_CHUNK - 1) / SCAN_CHUNK)   // 49

typedef unsigned short u16;
typedef unsigned long long ull;

// ---- scratch (device globals) ----
__device__ uint2  g_T1[NN * 32];   // conv1 per node/lane: (half2 eq*S, half2 ev*S)
__device__ uint2  g_T2[NN * 32];   // conv2 table
__device__ int    g_deg[NN];       // zero at start of every launch (self-cleaned)
__device__ int    g_rowptr[NN + 1];
__device__ u16    g_rank[EE];      // vectorized ushort4 access only
__device__ int    g_ssrc[EE];      // int: scattered stores must be full-word
__device__ int    g_bsum[SCAN_NB];
__device__ int    g_boff[SCAN_NB];
__device__ int    g_ctr;           // last-block counter (self-resetting)
__device__ int    g_ctr2;          // reset counter (self-resetting)
__device__ volatile int g_flag;    // scan barrier flag (self-resetting)

// ---- packed f32x2 helpers ----
__device__ __forceinline__ ull PK(float x, float y) {
    float2 f = make_float2(x, y);
    return *(ull*)&f;
}
__device__ __forceinline__ ull ADD2(ull a, ull b) {
    ull r; asm("add.rn.f32x2 %0, %1, %2;" : "=l"(r) : "l"(a), "l"(b)); return r;
}
__device__ __forceinline__ ull FMA2(ull a, ull b, ull c) {
    ull r; asm("fma.rn.f32x2 %0, %1, %2, %3;" : "=l"(r) : "l"(a), "l"(b), "l"(c)); return r;
}

// ---------------- CSR build (R13-proven plain launches) ----------------
__global__ void k_hist(const int4* __restrict__ dst4) {
    int i = blockIdx.x * blockDim.x + threadIdx.x;
    if (i < EE / 8) {
        int4 da = dst4[2 * i];
        int4 db = dst4[2 * i + 1];
        u16 a0 = (u16)atomicAdd(&g_deg[da.x], 1);
        u16 a1 = (u16)atomicAdd(&g_deg[da.y], 1);
        u16 a2 = (u16)atomicAdd(&g_deg[da.z], 1);
        u16 a3 = (u16)atomicAdd(&g_deg[da.w], 1);
        u16 b0 = (u16)atomicAdd(&g_deg[db.x], 1);
        u16 b1 = (u16)atomicAdd(&g_deg[db.y], 1);
        u16 b2 = (u16)atomicAdd(&g_deg[db.z], 1);
        u16 b3 = (u16)atomicAdd(&g_deg[db.w], 1);
        *(ushort4*)&g_rank[i * 8]     = make_ushort4(a0, a1, a2, a3);
        *(ushort4*)&g_rank[i * 8 + 4] = make_ushort4(b0, b1, b2, b3);
    }
}

__global__ void k_scanBC() {
    int t = threadIdx.x, b = blockIdx.x;
    int gbase = b * SCAN_CHUNK + t * 4;
    int4 v = make_int4(0, 0, 0, 0);
    if (gbase < NN) {
        v = *(const int4*)&g_deg[gbase];
        *(int4*)&g_deg[gbase] = make_int4(0, 0, 0, 0);   // self-clean
    }
    int tsum = v.x + v.y + v.z + v.w;
    int lane = t & 31, wid = t >> 5;
    int inc = tsum;
#pragma unroll
    for (int d = 1; d < 32; d <<= 1) {
        int a = __shfl_up_sync(0xffffffffu, inc, d);
        if (lane >= d) inc += a;
    }
    __shared__ int swp[8], soff[8], sTot, isLast;
    if (lane == 31) swp[wid] = inc;
    __syncthreads();
    if (t < 8) {
        int vb = swp[t];
        int ib = vb;
#pragma unroll
        for (int d = 1; d < 8; d <<= 1) {
            int a = __shfl_up_sync(0xffu, ib, d);
            if (t >= d) ib += a;
        }
        soff[t] = ib - vb;
        if (t == 7) sTot = ib;
    }
    __syncthreads();

    if (t == 0) {
        g_bsum[b] = sTot;
        __threadfence();
        int done = atomicAdd(&g_ctr, 1);
        isLast = (done == SCAN_NB - 1);
        if (isLast) g_ctr = 0;
    }
    __syncthreads();

    if (isLast) {
        if (t < 32) {
            __threadfence();
            int v0 = (t < SCAN_NB) ? g_bsum[t] : 0;
            int v1 = (t + 32 < SCAN_NB) ? g_bsum[t + 32] : 0;
            int i0 = v0, i1 = v1;
#pragma unroll
            for (int d = 1; d < 32; d <<= 1) {
                int a = __shfl_up_sync(0xffffffffu, i0, d);
                int b2 = __shfl_up_sync(0xffffffffu, i1, d);
                if (t >= d) { i0 += a; i1 += b2; }
            }
            int tot0 = __shfl_sync(0xffffffffu, i0, 31);
            if (t < SCAN_NB) g_boff[t] = i0 - v0;
            if (t + 32 < SCAN_NB) g_boff[t + 32] = tot0 + i1 - v1;
            if (t == 0) {
                g_rowptr[NN] = EE;
                __threadfence();
                g_flag = 1;
            }
        }
    } else {
        if (t == 0) { while (g_flag == 0) { } }
    }
    __syncthreads();

    if (gbase < NN) {
        int base = g_boff[b] + soff[wid] + inc - tsum;
        int4 r;
        r.x = base;
        r.y = base + v.x;
        r.z = r.y + v.y;
        r.w = r.z + v.z;
        *(int4*)&g_rowptr[gbase] = r;
    }
    __syncthreads();
    if (t == 0) {
        int d2 = atomicAdd(&g_ctr2, 1);
        if (d2 == SCAN_NB - 1) { g_ctr2 = 0; g_flag = 0; }
    }
}

// 8 edges per thread. PDL primary for conv1_proj2 (trigger at entry, R13-proven).
__global__ void k_scatter(const int4* __restrict__ src4, const int4* __restrict__ dst4) {
#if __CUDA_ARCH__ >= 900
    cudaTriggerProgrammaticLaunchCompletion();
#endif
    int i = blockIdx.x * blockDim.x + threadIdx.x;
    if (i < EE / 8) {
        int4 sa = *(const int4*)&src4[2 * i];
        int4 sb = *(const int4*)&src4[2 * i + 1];
        int4 da = *(const int4*)&dst4[2 * i];
        int4 db = *(const int4*)&dst4[2 * i + 1];
        ushort4 ra = *(const ushort4*)&g_rank[i * 8];
        ushort4 rb = *(const ushort4*)&g_rank[i * 8 + 4];
        int pa0 = __ldg(&g_rowptr[da.x]) + ra.x;
        int pa1 = __ldg(&g_rowptr[da.y]) + ra.y;
        int pa2 = __ldg(&g_rowptr[da.z]) + ra.z;
        int pa3 = __ldg(&g_rowptr[da.w]) + ra.w;
        int pb0 = __ldg(&g_rowptr[db.x]) + rb.x;
        int pb1 = __ldg(&g_rowptr[db.y]) + rb.y;
        int pb2 = __ldg(&g_rowptr[db.z]) + rb.z;
        int pb3 = __ldg(&g_rowptr[db.w]) + rb.w;
        g_ssrc[pa0] = sa.x; g_ssrc[pa1] = sa.y;
        g_ssrc[pa2] = sa.z; g_ssrc[pa3] = sa.w;
        g_ssrc[pb0] = sb.x; g_ssrc[pb1] = sb.y;
        g_ssrc[pb2] = sb.z; g_ssrc[pb3] = sb.w;
    }
}

// ---------------- fp16 table store ----------------
__device__ __forceinline__ void store_T(uint2* __restrict__ T, int node, int lane,
                                        float eq0, float eq1, float ev0, float ev1) {
    uint2 u;
    half2 heq = __floats2half2_rn(eq0 * TSCALE, eq1 * TSCALE);
    half2 hev = __floats2half2_rn(ev0 * TSCALE, ev1 * TSCALE);
    *(half2*)&u.x = heq;
    *(half2*)&u.y = hev;
    T[node * 32 + lane] = u;
}

// ---------------- conv1 projections (in=3) — no Dc store ----------------
__global__ void k_proj3(const float* __restrict__ x, const float* __restrict__ pos,
                        const float* __restrict__ Wsrc, const float* __restrict__ Wval,
                        const float* __restrict__ Wpos) {
    int lane = threadIdx.x & 31;
    int wid = threadIdx.x >> 5;
    int base = (blockIdx.x * 8 + wid) * 4;
    int c = 2 * lane;

    float2 ws0 = *(const float2*)&Wsrc[0 * HH + c];
    float2 ws1 = *(const float2*)&Wsrc[1 * HH + c];
    float2 ws2 = *(const float2*)&Wsrc[2 * HH + c];
    float2 wv0 = *(const float2*)&Wval[0 * HH + c];
    float2 wv1 = *(const float2*)&Wval[1 * HH + c];
    float2 wv2 = *(const float2*)&Wval[2 * HH + c];
    float2 wp0 = *(const float2*)&Wpos[0 * HH + c];
    float2 wp1 = *(const float2*)&Wpos[1 * HH + c];
    float2 wp2 = *(const float2*)&Wpos[2 * HH + c];

#pragma unroll
    for (int j = 0; j < 4; j++) {
        int node = base + j;
        if (node >= NN) break;
        float x0 = __ldg(&x[node * 3 + 0]);
        float x1 = __ldg(&x[node * 3 + 1]);
        float x2 = __ldg(&x[node * 3 + 2]);
        float p0 = __ldg(&pos[node * 3 + 0]);
        float p1 = __ldg(&pos[node * 3 + 1]);
        float p2 = __ldg(&pos[node * 3 + 2]);

        float qx = x0 * ws0.x + x1 * ws1.x + x2 * ws2.x;
        float qy = x0 * ws0.y + x1 * ws1.y + x2 * ws2.y;
        float vx = x0 * wv0.x + x1 * wv1.x + x2 * wv2.x;
        float vy = x0 * wv0.y + x1 * wv1.y + x2 * wv2.y;
        float ppx = p0 * wp0.x + p1 * wp1.x + p2 * wp2.x;
        float ppy = p0 * wp0.y + p1 * wp1.y + p2 * wp2.y;

        float eq0 = __expf(-(qx + ppx));
        float eq1 = __expf(-(qy + ppy));
        store_T(g_T1, node, lane, eq0, eq1, eq0 * (vx - ppx), eq1 * (vy - ppy));
    }
}

// ---------------- edge core (R8-proven; dc passed in) ----------------
__device__ __forceinline__ void acc1(const uint2* __restrict__ Tl, int sn, ull& s, ull& a) {
    uint2 t = __ldg(&Tl[sn * 32]);
    float2 eq = __half22float2(*(const half2*)&t.x);
    float2 ev = __half22float2(*(const half2*)&t.y);
    s = ADD2(s, PK(eq.x, eq.y));
    a = ADD2(a, PK(ev.x, ev.y));
}

__device__ __forceinline__ float2 edge_node(const uint2* __restrict__ T,
                                            int w, int lane, float2 dc) {
    int beg = __ldg(&g_rowptr[w]), end = __ldg(&g_rowptr[w + 1]);
    const uint2* Tl = &T[lane];
    ull s0 = 0ull, a0 = 0ull, s1 = 0ull, a1 = 0ull;

    for (int base = beg; base < end; base += 32) {
        int rem = end - base;
        int n = rem < 32 ? rem : 32;
        int idx = __ldg(&g_ssrc[base + (lane < n ? lane : 0)]);
        int j = 0;
        for (; j + 4 <= n; j += 4) {
            int sn0 = __shfl_sync(0xffffffffu, idx, j + 0);
            int sn1 = __shfl_sync(0xffffffffu, idx, j + 1);
            int sn2 = __shfl_sync(0xffffffffu, idx, j + 2);
            int sn3 = __shfl_sync(0xffffffffu, idx, j + 3);
            acc1(Tl, sn0, s0, a0);
            acc1(Tl, sn1, s1, a1);
            acc1(Tl, sn2, s0, a0);
            acc1(Tl, sn3, s1, a1);
        }
        for (; j < n; j++) {
            int sn = __shfl_sync(0xffffffffu, idx, j);
            acc1(Tl, sn, s0, a0);
        }
    }
    ull s = ADD2(s0, s1), a = ADD2(a0, a1);

    float2 r;
    if (end > beg) {
        float2 sf = *(float2*)&s;
        float2 af = *(float2*)&a;
        r.x = fmaxf(__fdividef(af.x, sf.x + 1e-12f) + dc.x, 0.f);
        r.y = fmaxf(__fdividef(af.y, sf.y + 1e-12f) + dc.y, 0.f);
    } else {
        r = make_float2(0.f, 0.f);
    }
    return r;
}

// ---- conv1 edge pass + conv2 projections, BLOCK-PHASE fused (R15-proven) ----
// Dc1 recomputed from pos & W1pos (no table); no Dc2 store (recomputed in head).
__global__ __launch_bounds__(512)
void k_conv1_proj2(const float* __restrict__ pos,
                   const float* __restrict__ W1pos, const float* __restrict__ b1pos,
                   const float* __restrict__ Wsrc, const float* __restrict__ Wval,
                   const float* __restrict__ Wpos) {
    __shared__ float shx[64][HH];      // 16 KB
    __shared__ ull sWs[HH * 32];       // 16 KB
    __shared__ ull sWv[HH * 32];       // 16 KB
    int tid = threadIdx.x;
    int lane = tid & 31, wid = tid >> 5;
    int nodeBase = blockIdx.x * 64;
    int c = 2 * lane;

#if __CUDA_ARCH__ >= 900
    cudaTriggerProgrammaticLaunchCompletion();
#endif

    // weight staging: reads INPUTS only — safe before grid-dep sync
    const ull* Ws8 = (const ull*)Wsrc;
    const ull* Wv8 = (const ull*)Wval;
    for (int i = tid; i < HH * 32; i += 512) {
        sWs[i] = Ws8[i];
        sWv[i] = Wv8[i];
    }

    // conv1 pos-proj weights (inputs): registers
    float2 u0 = *(const float2*)&W1pos[0 * HH + c];
    float2 u1 = *(const float2*)&W1pos[1 * HH + c];
    float2 u2 = *(const float2*)&W1pos[2 * HH + c];
    float2 b1 = *(const float2*)&b1pos[c];
    // conv2 pos-proj weights (inputs): registers
    float2 wp0 = *(const float2*)&Wpos[0 * HH + c];
    float2 wp1 = *(const float2*)&Wpos[1 * HH + c];
    float2 wp2 = *(const float2*)&Wpos[2 * HH + c];

    int n0 = wid * 4;
    // pos loads (inputs): hoist for all 4 nodes, compute dc1
    float px[4], py[4], pz[4];
    float2 dc1[4];
#pragma unroll
    for (int j = 0; j < 4; j++) {
        int node = nodeBase + n0 + j;
        int nc = node < NN ? node : 0;
        px[j] = __ldg(&pos[nc * 3 + 0]);
        py[j] = __ldg(&pos[nc * 3 + 1]);
        pz[j] = __ldg(&pos[nc * 3 + 2]);
        float ppx = px[j] * u0.x + py[j] * u1.x + pz[j] * u2.x;
        float ppy = px[j] * u0.y + py[j] * u1.y + pz[j] * u2.y;
        dc1[j] = make_float2(ppx + b1.x, ppy + b1.y);
    }

#if __CUDA_ARCH__ >= 900
    cudaGridDependencySynchronize();   // wait for scatter (and all prior) to complete
#endif

#pragma unroll
    for (int j = 0; j < 4; j++) {
        int node = nodeBase + n0 + j;
        float2 hv;
        if (node < NN) hv = edge_node(g_T1, node, lane, dc1[j]);
        else           hv = make_float2(0.f, 0.f);
        *(float2*)&shx[n0 + j][2 * lane] = hv;
    }
    __syncthreads();

    ull aS[4], aV[4];
#pragma unroll
    for (int j = 0; j < 4; j++) { aS[j] = 0ull; aV[j] = 0ull; }

#pragma unroll 8
    for (int k = 0; k < HH; k++) {
        ull ws = sWs[k * 32 + lane];
        ull wv = sWv[k * 32 + lane];
#pragma unroll
        for (int j = 0; j < 4; j++) {
            float xk = shx[n0 + j][k];
            ull xp = PK(xk, xk);
            aS[j] = FMA2(xp, ws, aS[j]);
            aV[j] = FMA2(xp, wv, aV[j]);
        }
    }

#pragma unroll
    for (int j = 0; j < 4; j++) {
        int node = nodeBase + n0 + j;
        if (node >= NN) break;
        float ppx = px[j] * wp0.x + py[j] * wp1.x + pz[j] * wp2.x;
        float ppy = px[j] * wp0.y + py[j] * wp1.y + pz[j] * wp2.y;
        float2 s = *(float2*)&aS[j];
        float2 v = *(float2*)&aV[j];
        float eq0 = __expf(-(s.x + ppx));
        float eq1 = __expf(-(s.y + ppy));
        store_T(g_T2, node, lane, eq0, eq1, eq0 * (v.x - ppx), eq1 * (v.y - ppy));
    }
}

// conv2 edge pass + MLP head (R15-proven). Dc2 recomputed from pos & W2pos.
__global__ __launch_bounds__(512)
void k_edge_head(const float* __restrict__ pos,
                 const float* __restrict__ W2pos, const float* __restrict__ b2pos,
                 const float* __restrict__ Wfc1, const float* __restrict__ bfc1,
                 const float* __restrict__ Wfc2, const float* __restrict__ bfc2,
                 float* __restrict__ out) {
    __shared__ float2 sW[32 * 32];   // sW[q*32+c] = (Wfc1[2q][c], Wfc1[2q+1][c])
    __shared__ float sb1[32], sW2[32];
    int tid = threadIdx.x;
    int lane = tid & 31, wid = tid >> 5;
    int c = 2 * lane;
    int w = blockIdx.x * 16 + wid;
    int wc = w < NN ? w : 0;

    // weight staging: inputs only — safe before grid-dep sync
    for (int i = tid; i < 1024; i += 512) {
        int q = i >> 5, cc = i & 31;
        sW[i] = make_float2(Wfc1[(2 * q) * 32 + cc], Wfc1[(2 * q + 1) * 32 + cc]);
    }
    if (tid < 32) { sb1[tid] = bfc1[tid]; sW2[tid] = Wfc2[tid]; }

    // dc2 from inputs: pos + W2pos + b2pos
    float2 u0 = *(const float2*)&W2pos[0 * HH + c];
    float2 u1 = *(const float2*)&W2pos[1 * HH + c];
    float2 u2 = *(const float2*)&W2pos[2 * HH + c];
    float2 b2p = *(const float2*)&b2pos[c];
    float p0 = __ldg(&pos[wc * 3 + 0]);
    float p1 = __ldg(&pos[wc * 3 + 1]);
    float p2 = __ldg(&pos[wc * 3 + 2]);
    float ppx = p0 * u0.x + p1 * u1.x + p2 * u2.x;
    float ppy = p0 * u0.y + p1 * u1.y + p2 * u2.y;
    float2 dc2 = make_float2(ppx + b2p.x, ppy + b2p.y);

#if __CUDA_ARCH__ >= 900
    cudaGridDependencySynchronize();   // wait for conv1_proj2 to complete
#endif
    __syncthreads();

    if (w >= NN) return;
    float2 hv = edge_node(g_T2, w, lane, dc2);

    float acc = sb1[lane];
#pragma unroll
    for (int q = 0; q < 32; q++) {
        float hx = __shfl_sync(0xffffffffu, hv.x, q);
        float hy = __shfl_sync(0xffffffffu, hv.y, q);
        float2 wv = sW[q * 32 + lane];
        acc = fmaf(hx, wv.x, fmaf(hy, wv.y, acc));
    }
    acc = fmaxf(acc, 0.f);
    float y = acc * sW2[lane];
#pragma unroll
    for (int off = 16; off; off >>= 1) y += __shfl_xor_sync(0xffffffffu, y, off);
    if (lane == 0) out[w] = y + bfc2[0];
}

extern "C" void kernel_launch(void* const* d_in, const int* in_sizes, int n_in,
                              void* d_out, int out_size) {
    const float* x    = (const float*)d_in[0];
    const float* pos  = (const float*)d_in[1];
    const int*   ei   = (const int*)d_in[2];
    const float* W1s  = (const float*)d_in[4];
    const float* W1v  = (const float*)d_in[6];
    const float* W1p  = (const float*)d_in[7];
    const float* b1p  = (const float*)d_in[8];
    const float* W2s  = (const float*)d_in[9];
    const float* W2v  = (const float*)d_in[11];
    const float* W2p  = (const float*)d_in[12];
    const float* b2p  = (const float*)d_in[13];
    const float* Wf1  = (const float*)d_in[14];
    const float* bf1  = (const float*)d_in[15];
    const float* Wf2  = (const float*)d_in[16];
    const float* bf2  = (const float*)d_in[17];
    float* out = (float*)d_out;

    const int4* src4 = (const int4*)ei;
    const int4* dst4 = (const int4*)(ei + EE);

    int vec8Grid = (EE / 8 + 255) / 256;   // 391

    cudaStream_t s2;
    cudaStreamCreateWithFlags(&s2, cudaStreamNonBlocking);
    cudaEvent_t evF, evP;
    cudaEventCreateWithFlags(&evF, cudaEventDisableTiming);
    cudaEventCreateWithFlags(&evP, cudaEventDisableTiming);

    // fork: proj3 on side stream
    cudaEventRecord(evF, 0);
    cudaStreamWaitEvent(s2, evF, 0);
    k_proj3<<<(NN + 31) / 32, 256, 0, s2>>>(x, pos, W1s, W1v, W1p);
    cudaEventRecord(evP, s2);

    // CSR chain on main stream (plain launches — R13-proven)
    k_hist<<<vec8Grid, 256>>>(dst4);
    k_scanBC<<<SCAN_NB, 256>>>();
    cudaStreamWaitEvent(0, evP, 0);        // proj3 long done by now: free join
    k_scatter<<<vec8Grid, 256>>>(src4, dst4);

    // PDL launches for the two big edge kernels (R13-proven win)
    cudaLaunchAttribute attrs[1];
    attrs[0].id = cudaLaunchAttributeProgrammaticStreamSerialization;
    attrs[0].val.programmaticStreamSerializationAllowed = 1;

    {
        cudaLaunchConfig_t cfg = {};
        cfg.gridDim = dim3((NN + 63) / 64);
        cfg.blockDim = dim3(512);
        cfg.stream = 0;
        cfg.attrs = attrs;
        cfg.numAttrs = 1;
        cudaLaunchKernelEx(&cfg, k_conv1_proj2, pos, W1p, b1p, W2s, W2v, W2p);
    }
    {
        cudaLaunchConfig_t cfg = {};
        cfg.gridDim = dim3((NN + 15) / 16);
        cfg.blockDim = dim3(512);
        cfg.stream = 0;
        cfg.attrs = attrs;
        cfg.numAttrs = 1;
        cudaLaunchKernelEx(&cfg, k_edge_head, pos, W2p, b2p, Wf1, bf1, Wf2, bf2, out);
    }
}